// round 8
// baseline (speedup 1.0000x reference)
#include <cuda_runtime.h>

#define BATCH 32
#define SEQ   512
#define HID   256
#define TMEL  2000
#define H4    (HID / 4)      // 64 float4 per row
#define CHUNK 16             // input rows per CTA
#define NCHUNK (SEQ / CHUNK) // 32 CTAs per batch
#define DMAX  8              // durations are in [0, 8)

__global__ __launch_bounds__(256, 6)
void length_regulator_kernel(const float* __restrict__ x,
                             const int* __restrict__ duration,
                             float* __restrict__ out,
                             int out_size) {
    const int b     = blockIdx.y;
    const int chunk = blockIdx.x;        // 0..31
    const int tid   = threadIdx.x;
    const int wid   = tid >> 5;
    const int lane5 = tid & 31;
    const int lane  = tid & 63;          // float4 slot within a row
    const int grp   = tid >> 6;          // 0..3 (row group)

    __shared__ int csum[SEQ];
    __shared__ int wsum[8];

    // ---- Front-batched loads: this group's 4 input rows (static addresses,
    //      independent of the scan -> latency hides under the prologue). ----
    const float4* __restrict__ xb = (const float4*)x + (b * SEQ) * H4;
    const int r0 = chunk * CHUNK + grp * 4;       // rows r0..r0+3
    float4 v[4];
    #pragma unroll
    for (int k = 0; k < 4; k++)
        v[k] = __ldg(&xb[(r0 + k) * H4 + lane]);

    // ---- Inclusive scan of all 512 durations (shuffle-based, 2 barriers). ----
    const int2* dur2 = (const int2*)(duration + b * SEQ);
    int2 d = dur2[tid];
    int sc = d.x + d.y;
    #pragma unroll
    for (int off = 1; off < 32; off <<= 1) {
        int t = __shfl_up_sync(0xffffffffu, sc, off);
        if (lane5 >= off) sc += t;
    }
    if (lane5 == 31) wsum[wid] = sc;
    __syncthreads();
    int wprefix = 0;
    #pragma unroll
    for (int w = 0; w < 8; w++)
        wprefix += (w < wid) ? wsum[w] : 0;
    int inc_hi = sc + wprefix;                    // cumsum at elem 2*tid+1
    csum[2 * tid]     = inc_hi - d.y;
    csum[2 * tid + 1] = inc_hi;
    __syncthreads();

    // ---- Input-driven expansion, BRANCHLESS: row i covers output rows
    //      [csum[i-1], csum[i]); duration < DMAX, so a fixed 8-slot
    //      predicated unroll replaces the serial data-dependent loop.
    //      32 independent predicated STG.128s pipeline at LSU rate. ----
    float4* __restrict__ ob = (float4*)out + (b * TMEL) * H4;
    #pragma unroll
    for (int k = 0; k < 4; k++) {
        int i  = r0 + k;
        int lo = (i == 0) ? 0 : csum[i - 1];
        int hi = min(csum[i], TMEL);
        #pragma unroll
        for (int j = 0; j < DMAX; j++) {
            int t = lo + j;
            if (t < hi)
                ob[t * H4 + lane] = v[k];
        }
    }

    // ---- Tail: positions [total, TMEL) replicate row SEQ-1. Spread across
    //      the 128 (chunk,grp) slots of this batch, stride 128. ----
    int total = csum[SEQ - 1];
    int tc = min(total, TMEL);
    int tstart = tc + chunk * 4 + grp;
    if (tstart < TMEL) {
        float4 vlast = __ldg(&xb[(SEQ - 1) * H4 + lane]);
        for (int t = tstart; t < TMEL; t += 4 * NCHUNK)
            ob[t * H4 + lane] = vlast;
    }

    // ---- mel_len appended after main output (if buffer includes it). ----
    if (chunk == 0 && tid == 0) {
        const int main_elems = BATCH * TMEL * HID;
        if (out_size >= main_elems + BATCH)
            out[main_elems + b] = (float)tc;
    }
}

extern "C" void kernel_launch(void* const* d_in, const int* in_sizes, int n_in,
                              void* d_out, int out_size) {
    const float* x        = (const float*)d_in[0];
    const int*   duration = (const int*)d_in[1];
    float*       out      = (float*)d_out;

    dim3 grid(NCHUNK, BATCH);   // (32, 32)
    length_regulator_kernel<<<grid, 256>>>(x, duration, out, out_size);
}

// round 9
// speedup vs baseline: 1.0194x; 1.0194x over previous
#include <cuda_runtime.h>

#define BATCH 32
#define SEQ   512
#define HID   256
#define TMEL  2000
#define H4    (HID / 4)      // 64 float4 per row
#define CHUNK 16             // input rows per CTA
#define NCHUNK (SEQ / CHUNK) // 32 CTAs per batch
#define DMAX  8              // durations are in [0, 8)

__global__ __launch_bounds__(256, 8)   // force 32 regs -> 8 CTA/SM -> single wave
void length_regulator_kernel(const float* __restrict__ x,
                             const int* __restrict__ duration,
                             float* __restrict__ out,
                             int out_size) {
    const int b     = blockIdx.y;
    const int chunk = blockIdx.x;        // 0..31
    const int tid   = threadIdx.x;
    const int wid   = tid >> 5;
    const int lane5 = tid & 31;
    const int lane  = tid & 63;          // float4 slot within a row
    const int grp   = tid >> 6;          // 0..3 (row group)

    __shared__ int csum[SEQ];
    __shared__ int wsum[8];

    // ---- Front-batched loads: this group's 4 input rows (static addresses,
    //      independent of the scan -> latency hides under the prologue). ----
    const float4* __restrict__ xb = (const float4*)x + (b * SEQ) * H4;
    const int r0 = chunk * CHUNK + grp * 4;       // rows r0..r0+3
    float4 v[4];
    #pragma unroll
    for (int k = 0; k < 4; k++)
        v[k] = __ldg(&xb[(r0 + k) * H4 + lane]);

    // ---- Inclusive scan of all 512 durations (shuffle-based, 2 barriers). ----
    const int2* dur2 = (const int2*)(duration + b * SEQ);
    int2 d = dur2[tid];
    int sc = d.x + d.y;
    #pragma unroll
    for (int off = 1; off < 32; off <<= 1) {
        int t = __shfl_up_sync(0xffffffffu, sc, off);
        if (lane5 >= off) sc += t;
    }
    if (lane5 == 31) wsum[wid] = sc;
    __syncthreads();
    int wprefix = 0;
    #pragma unroll
    for (int w = 0; w < 8; w++)
        wprefix += (w < wid) ? wsum[w] : 0;
    int inc_hi = sc + wprefix;                    // cumsum at elem 2*tid+1
    csum[2 * tid]     = inc_hi - d.y;
    csum[2 * tid + 1] = inc_hi;
    __syncthreads();

    // ---- Input-driven expansion, branchless: row i covers output rows
    //      [csum[i-1], csum[i]); duration < DMAX, so a fixed 8-slot
    //      predicated unroll; 32 independent predicated STG.128s. ----
    float4* __restrict__ ob = (float4*)out + (b * TMEL) * H4;
    #pragma unroll
    for (int k = 0; k < 4; k++) {
        int i  = r0 + k;
        int lo = (i == 0) ? 0 : csum[i - 1];
        int hi = min(csum[i], TMEL);
        #pragma unroll
        for (int j = 0; j < DMAX; j++) {
            int t = lo + j;
            if (t < hi)
                ob[t * H4 + lane] = v[k];
        }
    }

    // ---- Tail: positions [total, TMEL) replicate row SEQ-1. Spread across
    //      the 128 (chunk,grp) slots of this batch, stride 128. ----
    int total = csum[SEQ - 1];
    int tc = min(total, TMEL);
    int tstart = tc + chunk * 4 + grp;
    if (tstart < TMEL) {
        float4 vlast = __ldg(&xb[(SEQ - 1) * H4 + lane]);
        for (int t = tstart; t < TMEL; t += 4 * NCHUNK)
            ob[t * H4 + lane] = vlast;
    }

    // ---- mel_len appended after main output (if buffer includes it). ----
    if (chunk == 0 && tid == 0) {
        const int main_elems = BATCH * TMEL * HID;
        if (out_size >= main_elems + BATCH)
            out[main_elems + b] = (float)tc;
    }
}

extern "C" void kernel_launch(void* const* d_in, const int* in_sizes, int n_in,
                              void* d_out, int out_size) {
    const float* x        = (const float*)d_in[0];
    const int*   duration = (const int*)d_in[1];
    float*       out      = (float*)d_out;

    dim3 grid(NCHUNK, BATCH);   // (32, 32) = 1024 CTAs, one wave at occ 8
    length_regulator_kernel<<<grid, 256>>>(x, duration, out, out_size);
}